// round 12
// baseline (speedup 1.0000x reference)
#include <cuda_runtime.h>
#include <cuda_fp16.h>
#include <cstdint>

#define NN 50000
#define EE 800000
#define DD 128
#define HH 8

// ---------------- scratch (static device arrays; no allocation) ------------
__device__ float g_QKV[(size_t)NN * 384];
__device__ float g_P [(size_t)EE * DD];      // proj_e
__device__ float g_wV[(size_t)NN * DD];
__device__ float g_z [(size_t)NN * HH];
__device__ float g_bqkv[384];

// fp16 weights, [n][k] layout, packed
#define OF_QKV  0
#define OF_WE   49152
#define OF_WON  65536
#define OF_WOE  81920
#define OF_W1N  98304
#define OF_W2N  131072
#define OF_W1E  163840
#define OF_W2E  196608
#define W_TOT   229376
__device__ __half g_WF[W_TOT];

// =================== helpers ===============================================
__device__ __forceinline__ void mma_f16(float *c, const uint32_t *a,
                                        const uint32_t *b) {
    asm volatile(
        "mma.sync.aligned.m16n8k16.row.col.f32.f16.f16.f32 "
        "{%0,%1,%2,%3}, {%4,%5,%6,%7}, {%8,%9}, {%0,%1,%2,%3};"
        : "+f"(c[0]), "+f"(c[1]), "+f"(c[2]), "+f"(c[3])
        : "r"(a[0]), "r"(a[1]), "r"(a[2]), "r"(a[3]), "r"(b[0]), "r"(b[1]));
}
__device__ __forceinline__ void ldsm4(uint32_t *r, uint32_t addr) {
    asm volatile("ldmatrix.sync.aligned.m8n8.x4.shared.b16 {%0,%1,%2,%3}, [%4];"
                 : "=r"(r[0]), "=r"(r[1]), "=r"(r[2]), "=r"(r[3]) : "r"(addr));
}
__device__ __forceinline__ uint32_t pack_h2(float x, float y) {
    __half2 t = __floats2half2_rn(x, y);
    return *reinterpret_cast<uint32_t *>(&t);
}
__device__ __forceinline__ void cp16(uint32_t saddr, const void *g) {
    asm volatile("cp.async.cg.shared.global [%0], [%1], 16;"
                 :: "r"(saddr), "l"(g));
}
#define CP_COMMIT() asm volatile("cp.async.commit_group;" ::: "memory")
#define CP_WAIT(n)  asm volatile("cp.async.wait_group %0;" :: "n"(n) : "memory")
#define CLIP5(x) fminf(fmaxf((x), -5.f), 5.f)

#define SSTR 136     // A smem stride (fp16)
#define WSTR 72      // W tile stride (fp16)
#define EST  132     // epilogue staging stride (fp32)

// one 64x128(A rows) x [128n x 64k](B) fp16 MMA pass:
// 8 warps as 2(M: mw) x 4(N: nw), each warp 32x32.
__device__ __forceinline__ void mma_tile(
    float acc[2][4][4],
    const char *A, int kbase, const char *B,
    int mw, int nw, int lane)
{
    const uint32_t aoff = (uint32_t)(((mw * 32 + (lane & 15)) * SSTR +
                                      kbase + (lane >> 4) * 8) * 2);
    const uint32_t boff = (uint32_t)(((nw * 32 + ((lane >> 4) & 1) * 8 + (lane & 7)) * WSTR +
                                      ((lane >> 3) & 1) * 8) * 2);
    const uint32_t aB = (uint32_t)__cvta_generic_to_shared(A) + aoff;
    const uint32_t bB = (uint32_t)__cvta_generic_to_shared(B) + boff;

    #pragma unroll
    for (int kk = 0; kk < 4; kk++) {
        const uint32_t ka = kk * 32;
        uint32_t a[2][4], b[2][4];
        ldsm4(a[0], aB + ka);
        ldsm4(a[1], aB + ka + 16 * SSTR * 2);
        ldsm4(b[0], bB + ka);
        ldsm4(b[1], bB + ka + 16 * WSTR * 2);
        #pragma unroll
        for (int j = 0; j < 4; j++) {
            const uint32_t *bp = &b[j >> 1][2 * (j & 1)];
            mma_f16(acc[0][j], a[0], bp);
            mma_f16(acc[1][j], a[1], bp);
        }
    }
}

// cp.async load of a [128n x 64k] fp16 W tile, 256 threads
__device__ __forceinline__ void loadW(
    char *smem_w, const __half *W,
    int Kw, int nrow_base, int kofs, int tid)
{
    #pragma unroll
    for (int h = 0; h < 2; h++) {
        const int n = (tid >> 2) + h * 64;
        const int q = (tid & 3) * 16;
        const size_t g = (size_t)(nrow_base + n) * Kw + kofs + q;
        const uint32_t d = (uint32_t)__cvta_generic_to_shared(smem_w + (n * WSTR + q) * 2);
        cp16(d, W + g);
        cp16(d + 16, W + g + 8);
    }
}

// LN over 128 features, interleaved layout: thread owns cols cb+16i (4 each)
__device__ __forceinline__ void ln_row(float4 v[8], const float *lnw,
                                       const float *lnb, int cb)
{
    float s = 0.f, q = 0.f;
    #pragma unroll
    for (int i = 0; i < 8; i++) {
        s += v[i].x + v[i].y + v[i].z + v[i].w;
        q += v[i].x * v[i].x + v[i].y * v[i].y + v[i].z * v[i].z + v[i].w * v[i].w;
    }
    s += __shfl_xor_sync(0xffffffffu, s, 1);
    s += __shfl_xor_sync(0xffffffffu, s, 2);
    q += __shfl_xor_sync(0xffffffffu, q, 1);
    q += __shfl_xor_sync(0xffffffffu, q, 2);
    const float m  = s * (1.f / 128.f);
    const float rs = rsqrtf(q * (1.f / 128.f) - m * m + 1e-5f);
    #pragma unroll
    for (int i = 0; i < 8; i++) {
        const int gc = cb + i * 16;
        v[i].x = (v[i].x - m) * rs * lnw[gc + 0] + lnb[gc + 0];
        v[i].y = (v[i].y - m) * rs * lnw[gc + 1] + lnb[gc + 1];
        v[i].z = (v[i].z - m) * rs * lnw[gc + 2] + lnb[gc + 2];
        v[i].w = (v[i].w - m) * rs * lnw[gc + 3] + lnb[gc + 3];
    }
}
__device__ __forceinline__ void store_cvt(uint32_t *Au, const float4 v[8],
                                          int r, int cb)
{
    #pragma unroll
    for (int i = 0; i < 8; i++) {
        const int idx = (r * SSTR + cb + i * 16) >> 1;
        Au[idx]     = pack_h2(v[i].x, v[i].y);
        Au[idx + 1] = pack_h2(v[i].z, v[i].w);
    }
}

// staged epilogue: fragments -> smem (2 row passes) -> coalesced f4 stores
__device__ __forceinline__ void epi_store(
    float acc[2][4][4], float *St, int mw, int nw, int lane, int tid,
    int row0, int colbase, const float *bias, const float *resid,
    float *Y, int ldy, int R)
{
    #pragma unroll
    for (int pass = 0; pass < 2; pass++) {
        __syncthreads();
        if (mw == pass) {
            #pragma unroll
            for (int mt = 0; mt < 2; mt++)
                #pragma unroll
                for (int half = 0; half < 2; half++)
                    #pragma unroll
                    for (int j = 0; j < 4; j++) {
                        const int rl = mt * 16 + half * 8 + (lane >> 2);
                        const int cl = nw * 32 + j * 8 + 2 * (lane & 3);
                        float2 o;
                        o.x = acc[mt][j][half * 2 + 0];
                        o.y = acc[mt][j][half * 2 + 1];
                        *reinterpret_cast<float2 *>(St + rl * EST + cl) = o;
                    }
        }
        __syncthreads();
        const int r2 = tid >> 3;
        const int gr = row0 + pass * 32 + r2;
        if (gr < R) {
            #pragma unroll
            for (int n = 0; n < 4; n++) {
                const int c = (tid & 7) * 4 + n * 32;
                float4 o = *reinterpret_cast<const float4 *>(St + r2 * EST + c);
                const int col = colbase + c;
                if (bias) {
                    const float4 b = *reinterpret_cast<const float4 *>(bias + col);
                    o.x += b.x; o.y += b.y; o.z += b.z; o.w += b.w;
                }
                const size_t yb = (size_t)gr * ldy + col;
                if (resid) {
                    const float4 rv = *reinterpret_cast<const float4 *>(resid + yb);
                    o.x += rv.x; o.y += rv.y; o.z += rv.z; o.w += rv.w;
                }
                *reinterpret_cast<float4 *>(Y + yb) = o;
            }
        }
    }
}

// ======================= generic pipelined GEMM (64-row tiles) =============
#define G_A  0
#define G_W  17408
#define G_SLOT 18432
#define G_ST (G_W + 2 * G_SLOT)            // 54272
#define G_TOT (G_ST + 32 * EST * 4)        // 71168

__global__ void __launch_bounds__(256, 3) tcgemm(
    const float *__restrict__ X, int ldx,
    const float *__restrict__ lnw, const float *__restrict__ lnb,
    const float *__restrict__ zdiv,
    const __half *__restrict__ W,
    int No, const float *__restrict__ bias, const float *__restrict__ resid,
    float *__restrict__ Y, int ldy, int R)
{
    extern __shared__ char smc[];
    char *Ac = smc + G_A;
    uint32_t *Au = reinterpret_cast<uint32_t *>(Ac);
    float *St = reinterpret_cast<float *>(smc + G_ST);

    const int tid  = threadIdx.x;
    const int wid  = tid >> 5;
    const int lane = tid & 31;
    const int mw   = wid & 1;
    const int nw   = wid >> 1;
    const int row0 = blockIdx.x * 64;
    const bool do_ln = (lnw != nullptr);
    const int T = (No >> 7) * 2;

    loadW(smc + G_W,          W, 128, 0, 0, tid);  CP_COMMIT();
    loadW(smc + G_W + G_SLOT, W, 128, 0, 64, tid); CP_COMMIT();

    // ---- A: 64 rows, interleaved cols cb + 16i ----------------------------
    {
        const int r  = tid >> 2;
        const int cb = (tid & 3) * 4;
        const int grow = row0 + r;
        const bool valid = grow < R;
        const float *xr = X + (size_t)grow * ldx;
        float4 v[8];
        if (valid) {
            #pragma unroll
            for (int i = 0; i < 8; i++)
                v[i] = *reinterpret_cast<const float4 *>(xr + cb + i * 16);
        } else {
            #pragma unroll
            for (int i = 0; i < 8; i++) v[i] = make_float4(0.f, 0.f, 0.f, 0.f);
        }
        if (zdiv && valid) {
            // head of v[i] is exactly i
            const float4 z0 = *reinterpret_cast<const float4 *>(zdiv + (size_t)grow * 8);
            const float4 z1 = *reinterpret_cast<const float4 *>(zdiv + (size_t)grow * 8 + 4);
            float zi[8] = {z0.x, z0.y, z0.z, z0.w, z1.x, z1.y, z1.z, z1.w};
            #pragma unroll
            for (int i = 0; i < 8; i++) {
                const float s = 1.f / (zi[i] + 1e-8f);
                v[i].x *= s; v[i].y *= s; v[i].z *= s; v[i].w *= s;
            }
        }
        if (do_ln) ln_row(v, lnw, lnb, cb);
        store_cvt(Au, v, r, cb);
    }

    float acc[2][4][4];
    for (int t = 0; t < T; t++) {
        const int nt = t >> 1;
        if (!(t & 1)) {
            #pragma unroll
            for (int mt = 0; mt < 2; mt++)
                #pragma unroll
                for (int j = 0; j < 4; j++)
                    #pragma unroll
                    for (int q = 0; q < 4; q++) acc[mt][j][q] = 0.f;
        }
        if (t < T - 1) { CP_WAIT(1); } else { CP_WAIT(0); }
        __syncthreads();
        char *sh = smc + G_W + (t & 1) * G_SLOT;
        mma_tile(acc, Ac, (t & 1) * 64, sh, mw, nw, lane);
        __syncthreads();
        if (t + 2 < T) {
            loadW(sh, W, 128, ((t + 2) >> 1) * 128, ((t + 2) & 1) * 64, tid);
            CP_COMMIT();
        }
        if (t & 1)
            epi_store(acc, St, mw, nw, lane, tid, row0, nt * 128,
                      bias, resid, Y, ldy, R);
    }
}

// ======================= fused LN2 + MLP chain (64-row) ====================
#define C_A  0
#define C_H  17408
#define C_W  34816
#define C_ST 53248
#define C_TOT (C_ST + 32 * EST * 4)        // 70144

__global__ void __launch_bounds__(256, 3) mlp_chain(
    float *__restrict__ Y,
    const float *__restrict__ lnw, const float *__restrict__ lnb,
    const __half *__restrict__ W1, const __half *__restrict__ W2,
    int R)
{
    extern __shared__ char smc[];
    char *Ac = smc + C_A;  char *Hc = smc + C_H;
    uint32_t *Au = reinterpret_cast<uint32_t *>(Ac);
    uint32_t *Hu = reinterpret_cast<uint32_t *>(Hc);
    char *wc = smc + C_W;
    float *St = reinterpret_cast<float *>(smc + C_ST);

    const int tid  = threadIdx.x;
    const int wid  = tid >> 5;
    const int lane = tid & 31;
    const int mw   = wid & 1;
    const int nw   = wid >> 1;
    const int row0 = blockIdx.x * 64;

    loadW(wc, W1, 128, 0, 0, tid); CP_COMMIT();

    // ---- A: 64 rows + LN2, interleaved ------------------------------------
    {
        const int r  = tid >> 2;
        const int cb = (tid & 3) * 4;
        const int grow = row0 + r;
        const bool valid = grow < R;
        const float *xr = Y + (size_t)grow * 128;
        float4 v[8];
        if (valid) {
            #pragma unroll
            for (int i = 0; i < 8; i++)
                v[i] = *reinterpret_cast<const float4 *>(xr + cb + i * 16);
        } else {
            #pragma unroll
            for (int i = 0; i < 8; i++) v[i] = make_float4(0.f, 0.f, 0.f, 0.f);
        }
        ln_row(v, lnw, lnb, cb);
        store_cvt(Au, v, r, cb);
    }

    float acc1[2][4][4], acc2[2][4][4];
    #pragma unroll
    for (int mt = 0; mt < 2; mt++)
        #pragma unroll
        for (int j = 0; j < 4; j++)
            #pragma unroll
            for (int q = 0; q < 4; q++) acc2[mt][j][q] = 0.f;

    #pragma unroll
    for (int h = 0; h < 2; h++) {
        #pragma unroll
        for (int mt = 0; mt < 2; mt++)
            #pragma unroll
            for (int j = 0; j < 4; j++)
                #pragma unroll
                for (int q = 0; q < 4; q++) acc1[mt][j][q] = 0.f;

        if (h == 1) { loadW(wc, W1, 128, 128, 0, tid); CP_COMMIT(); }
        CP_WAIT(0); __syncthreads();
        mma_tile(acc1, Ac, 0, wc, mw, nw, lane);
        __syncthreads();
        loadW(wc, W1, 128, h * 128, 64, tid); CP_COMMIT();
        CP_WAIT(0); __syncthreads();
        mma_tile(acc1, Ac, 64, wc, mw, nw, lane);

        // silu -> H (smem only, fragment layout)
        #pragma unroll
        for (int mt = 0; mt < 2; mt++)
            #pragma unroll
            for (int qh = 0; qh < 2; qh++)
                #pragma unroll
                for (int j = 0; j < 4; j++) {
                    const int rl = mw * 32 + mt * 16 + (lane >> 2) + qh * 8;
                    const int cl = nw * 32 + j * 8 + 2 * (lane & 3);
                    float x = acc1[mt][j][qh * 2 + 0];
                    float y = acc1[mt][j][qh * 2 + 1];
                    x = x / (1.f + __expf(-x));
                    y = y / (1.f + __expf(-y));
                    Hu[(rl * SSTR + cl) >> 1] = pack_h2(x, y);
                }
        __syncthreads();

        // acc2 += H @ W2[:, h*128 : h*128+128]
        loadW(wc, W2, 256, 0, h * 128, tid); CP_COMMIT();
        CP_WAIT(0); __syncthreads();
        mma_tile(acc2, Hc, 0, wc, mw, nw, lane);
        __syncthreads();
        loadW(wc, W2, 256, 0, h * 128 + 64, tid); CP_COMMIT();
        CP_WAIT(0); __syncthreads();
        mma_tile(acc2, Hc, 64, wc, mw, nw, lane);
        __syncthreads();
    }

    // staged epilogue: + resid (Y), in place
    epi_store(acc2, St, mw, nw, lane, tid, row0, 0, nullptr, Y, Y, 128, R);
}

// ======================= fused edge attention + Wo_e (64-row) ==============
#define T_A  0
#define T_W  17408
#define T_SLOT 18432
#define T_ST (T_W + 2 * T_SLOT)            // 54272
#define T_TOT (T_ST + 32 * EST * 4)        // 71168

__global__ void __launch_bounds__(256, 3) attn_gemm(
    const float *__restrict__ P, const float *__restrict__ QKV,
    const int *__restrict__ src, const int *__restrict__ dst,
    const __half *__restrict__ W,
    const float *__restrict__ bias, const float *__restrict__ resid,
    float *__restrict__ wV, float *__restrict__ z,
    float *__restrict__ Y)
{
    extern __shared__ char smc[];
    char *Ac = smc + T_A;
    uint32_t *Au = reinterpret_cast<uint32_t *>(Ac);
    char *w0 = smc + T_W;
    char *w1 = smc + T_W + T_SLOT;
    float *St = reinterpret_cast<float *>(smc + T_ST);

    const int tid  = threadIdx.x;
    const int wid  = tid >> 5;
    const int lane = tid & 31;
    const int mw   = wid & 1;
    const int nw   = wid >> 1;
    const int row0 = blockIdx.x * 64;

    loadW(w0, W, 128, 0, 0, tid);  CP_COMMIT();
    loadW(w1, W, 128, 0, 64, tid); CP_COMMIT();

    // ---- A phase: per-edge attention, interleaved cols (head of v[i] = i) -
    {
        const int r  = tid >> 2;
        const int cb = (tid & 3) * 4;
        const int e  = row0 + r;               // EE % 64 == 0: always valid
        const int s = src[e];
        const int d = dst[e];
        const float *pr = P   + (size_t)e * 128;
        const float *kr = QKV + (size_t)s * 384 + 128;
        const float *qr = QKV + (size_t)d * 384;
        const float *vr = QKV + (size_t)s * 384 + 256;

        float4 eo[8];
        float hs[8];
        #pragma unroll
        for (int i = 0; i < 8; i++) {
            const int c = cb + i * 16;
            const float4 kv = *reinterpret_cast<const float4 *>(kr + c);
            const float4 qv = *reinterpret_cast<const float4 *>(qr + c);
            const float4 pv = *reinterpret_cast<const float4 *>(pr + c);
            float4 t;
            t.x = CLIP5(kv.x * qv.x * 0.25f) * pv.x;
            t.y = CLIP5(kv.y * qv.y * 0.25f) * pv.y;
            t.z = CLIP5(kv.z * qv.z * 0.25f) * pv.z;
            t.w = CLIP5(kv.w * qv.w * 0.25f) * pv.w;
            eo[i] = t;
            hs[i] = t.x + t.y + t.z + t.w;
        }
        // reduce head sums across the 4 lanes of this row
        #pragma unroll
        for (int i = 0; i < 8; i++) {
            hs[i] += __shfl_xor_sync(0xffffffffu, hs[i], 1);
            hs[i] += __shfl_xor_sync(0xffffffffu, hs[i], 2);
        }
        float w[8];
        #pragma unroll
        for (int i = 0; i < 8; i++) w[i] = __expf(CLIP5(hs[i]));

        float *wvp = wV + (size_t)d * 128;
        #pragma unroll
        for (int i = 0; i < 8; i++) {
            const int c = cb + i * 16;
            const float4 vv = *reinterpret_cast<const float4 *>(vr + c);
            atomicAdd(wvp + c + 0, vv.x * w[i]);
            atomicAdd(wvp + c + 1, vv.y * w[i]);
            atomicAdd(wvp + c + 2, vv.z * w[i]);
            atomicAdd(wvp + c + 3, vv.w * w[i]);
        }
        // two z heads per lane: i = (tid&3), (tid&3)+4
        const int hz = tid & 3;
        atomicAdd(z + (size_t)d * 8 + hz,     w[hz]);
        atomicAdd(z + (size_t)d * 8 + hz + 4, w[hz + 4]);

        store_cvt(Au, eo, r, cb);
    }

    float acc[2][4][4];
    #pragma unroll
    for (int mt = 0; mt < 2; mt++)
        #pragma unroll
        for (int j = 0; j < 4; j++)
            #pragma unroll
            for (int q = 0; q < 4; q++) acc[mt][j][q] = 0.f;

    CP_WAIT(1); __syncthreads();
    mma_tile(acc, Ac, 0, w0, mw, nw, lane);
    CP_WAIT(0); __syncthreads();
    mma_tile(acc, Ac, 64, w1, mw, nw, lane);

    epi_store(acc, St, mw, nw, lane, tid, row0, 0, bias, resid, Y, 128, EE);
}

// --------------- single-launch weight convert/transpose --------------------
struct WDesc { const float *W; int K; int No; int ofs; int start; };
struct WPack { WDesc d[10]; int total; };

__global__ void split_all(WPack p, __half *__restrict__ out)
{
    int i = blockIdx.x * 256 + threadIdx.x;
    if (i >= p.total) return;
    #pragma unroll
    for (int m = 0; m < 10; m++) {
        const WDesc &d = p.d[m];
        const int sz = d.K * d.No;
        if (i < d.start + sz) {
            const int il = i - d.start;
            const int k = il / d.No;
            const int n = il - k * d.No;
            out[(size_t)d.ofs + (size_t)n * d.K + k] = __float2half(d.W[il]);
            return;
        }
    }
}

__global__ void pack_bias(const float *__restrict__ a, const float *__restrict__ b,
                          const float *__restrict__ c, float *__restrict__ o)
{
    const int i = threadIdx.x;
    if (i < 128) { o[i] = a[i]; o[128 + i] = b[i]; o[256 + i] = c[i]; }
}

// ---------------------------------------------------------------------------
extern "C" void kernel_launch(void *const *d_in, const int *in_sizes, int n_in,
                              void *d_out, int out_size)
{
    const float *node   = (const float *)d_in[0];
    const float *edge   = (const float *)d_in[1];
    const int   *src    = (const int *)d_in[2];
    const int   *dst    = (const int *)d_in[3];
    const float *ln1n_w = (const float *)d_in[4];
    const float *ln1n_b = (const float *)d_in[5];
    const float *ln1e_w = (const float *)d_in[6];
    const float *ln1e_b = (const float *)d_in[7];
    const float *ln2n_w = (const float *)d_in[8];
    const float *ln2n_b = (const float *)d_in[9];
    const float *ln2e_w = (const float *)d_in[10];
    const float *ln2e_b = (const float *)d_in[11];
    const float *Wq = (const float *)d_in[12];  const float *bq = (const float *)d_in[13];
    const float *Wk = (const float *)d_in[14];  const float *bk = (const float *)d_in[15];
    const float *Wv = (const float *)d_in[16];  const float *bv = (const float *)d_in[17];
    const float *We = (const float *)d_in[18];  const float *be = (const float *)d_in[19];
    const float *Wo_n = (const float *)d_in[20]; const float *bo_n = (const float *)d_in[21];
    const float *Wo_e = (const float *)d_in[22]; const float *bo_e = (const float *)d_in[23];
    const float *w1n = (const float *)d_in[24];
    const float *w2n = (const float *)d_in[25];
    const float *w1e = (const float *)d_in[26];
    const float *w2e = (const float *)d_in[27];

    float *outh = (float *)d_out;
    float *oute = outh + (size_t)NN * DD;

    float *QKVp, *Pp, *wVp, *zp, *bqkv;
    __half *WFp;
    cudaGetSymbolAddress((void **)&QKVp, g_QKV);
    cudaGetSymbolAddress((void **)&Pp,  g_P);
    cudaGetSymbolAddress((void **)&wVp, g_wV);
    cudaGetSymbolAddress((void **)&zp,  g_z);
    cudaGetSymbolAddress((void **)&bqkv, g_bqkv);
    cudaGetSymbolAddress((void **)&WFp, g_WF);

    cudaFuncSetAttribute(tcgemm,    cudaFuncAttributeMaxDynamicSharedMemorySize, G_TOT);
    cudaFuncSetAttribute(mlp_chain, cudaFuncAttributeMaxDynamicSharedMemorySize, C_TOT);
    cudaFuncSetAttribute(attn_gemm, cudaFuncAttributeMaxDynamicSharedMemorySize, T_TOT);

    WPack p;
    int st = 0;
    auto add = [&](int m, const float *W, int K, int No, int ofs) {
        p.d[m] = {W, K, No, ofs, st};
        st += K * No;
    };
    add(0, Wq, 128, 128, OF_QKV);
    add(1, Wk, 128, 128, OF_QKV + 16384);
    add(2, Wv, 128, 128, OF_QKV + 32768);
    add(3, We, 128, 128, OF_WE);
    add(4, Wo_n, 128, 128, OF_WON);
    add(5, Wo_e, 128, 128, OF_WOE);
    add(6, w1n, 128, 256, OF_W1N);
    add(7, w2n, 256, 128, OF_W2N);
    add(8, w1e, 128, 256, OF_W1E);
    add(9, w2e, 256, 128, OF_W2E);
    p.total = st;
    split_all<<<(st + 255) / 256, 256>>>(p, WFp);
    pack_bias<<<1, 128>>>(bq, bk, bv, bqkv);

    cudaMemsetAsync(wVp, 0, (size_t)NN * DD * sizeof(float), 0);
    cudaMemsetAsync(zp,  0, (size_t)NN * HH * sizeof(float), 0);

    const int GN = (NN + 63) / 64;
    const int GE = (EE + 63) / 64;

    // LN1 + fused QKV projection (No=384); LN1 + edge projection -> P
    tcgemm<<<GN, 256, G_TOT>>>(node, 128, ln1n_w, ln1n_b, nullptr,
                               WFp + OF_QKV, 384, bqkv, nullptr,
                               QKVp, 384, NN);
    tcgemm<<<GE, 256, G_TOT>>>(edge, 128, ln1e_w, ln1e_b, nullptr,
                               WFp + OF_WE, 128, be, nullptr,
                               Pp, 128, EE);

    // fused edge attention + Wo_e + resid -> oute (also scatters wV, z)
    attn_gemm<<<GE, 256, T_TOT>>>(Pp, QKVp, src, dst,
                                  WFp + OF_WOE, bo_e, edge,
                                  wVp, zp, oute);

    // node output projection: A = wV / z, + resid -> outh
    tcgemm<<<GN, 256, G_TOT>>>(wVp, 128, nullptr, nullptr, zp,
                               WFp + OF_WON, 128, bo_n, node,
                               outh, 128, NN);

    // fused LN2 + MLP + resid, in place
    mlp_chain<<<GN, 256, C_TOT>>>(outh, ln2n_w, ln2n_b,
                                  WFp + OF_W1N, WFp + OF_W2N, NN);
    mlp_chain<<<GE, 256, C_TOT>>>(oute, ln2e_w, ln2e_b,
                                  WFp + OF_W1E, WFp + OF_W2E, EE);
}

// round 14
// speedup vs baseline: 1.0664x; 1.0664x over previous
#include <cuda_runtime.h>
#include <cuda_fp16.h>
#include <cstdint>

#define NN 50000
#define EE 800000
#define DD 128
#define HH 8

// ---------------- scratch (static device arrays; no allocation) ------------
__device__ float g_QKV[(size_t)NN * 384];
__device__ float g_wV[(size_t)NN * DD];
__device__ float g_z [(size_t)NN * HH];
__device__ float g_bqkv[384];

// fp16 weights, [n][k] layout, packed
#define OF_QKV  0
#define OF_WE   49152
#define OF_WON  65536
#define OF_WOE  81920
#define OF_W1N  98304
#define OF_W2N  131072
#define OF_W1E  163840
#define OF_W2E  196608
#define W_TOT   229376
__device__ __half g_WF[W_TOT];

// =================== helpers ===============================================
__device__ __forceinline__ void mma_f16(float *c, const uint32_t *a,
                                        const uint32_t *b) {
    asm volatile(
        "mma.sync.aligned.m16n8k16.row.col.f32.f16.f16.f32 "
        "{%0,%1,%2,%3}, {%4,%5,%6,%7}, {%8,%9}, {%0,%1,%2,%3};"
        : "+f"(c[0]), "+f"(c[1]), "+f"(c[2]), "+f"(c[3])
        : "r"(a[0]), "r"(a[1]), "r"(a[2]), "r"(a[3]), "r"(b[0]), "r"(b[1]));
}
__device__ __forceinline__ void ldsm4(uint32_t *r, uint32_t addr) {
    asm volatile("ldmatrix.sync.aligned.m8n8.x4.shared.b16 {%0,%1,%2,%3}, [%4];"
                 : "=r"(r[0]), "=r"(r[1]), "=r"(r[2]), "=r"(r[3]) : "r"(addr));
}
__device__ __forceinline__ uint32_t pack_h2(float x, float y) {
    __half2 t = __floats2half2_rn(x, y);
    return *reinterpret_cast<uint32_t *>(&t);
}
__device__ __forceinline__ void cp16(uint32_t saddr, const void *g) {
    asm volatile("cp.async.cg.shared.global [%0], [%1], 16;"
                 :: "r"(saddr), "l"(g));
}
#define CP_COMMIT() asm volatile("cp.async.commit_group;" ::: "memory")
#define CP_WAIT(n)  asm volatile("cp.async.wait_group %0;" :: "n"(n) : "memory")
#define CLIP5(x) fminf(fmaxf((x), -5.f), 5.f)

#define SSTR 136     // A smem stride (fp16)
#define WSTR 72      // W tile stride (fp16)

// one 64x128(A rows) x [128n x 64k](B) fp16 MMA pass:
// 8 warps as 2(M: mw) x 4(N: nw), each warp 32x32.
__device__ __forceinline__ void mma_tile(
    float acc[2][4][4],
    const char *A, int kbase, const char *B,
    int mw, int nw, int lane)
{
    const uint32_t aoff = (uint32_t)(((mw * 32 + (lane & 15)) * SSTR +
                                      kbase + (lane >> 4) * 8) * 2);
    const uint32_t boff = (uint32_t)(((nw * 32 + ((lane >> 4) & 1) * 8 + (lane & 7)) * WSTR +
                                      ((lane >> 3) & 1) * 8) * 2);
    const uint32_t aB = (uint32_t)__cvta_generic_to_shared(A) + aoff;
    const uint32_t bB = (uint32_t)__cvta_generic_to_shared(B) + boff;

    #pragma unroll
    for (int kk = 0; kk < 4; kk++) {
        const uint32_t ka = kk * 32;
        uint32_t a[2][4], b[2][4];
        ldsm4(a[0], aB + ka);
        ldsm4(a[1], aB + ka + 16 * SSTR * 2);
        ldsm4(b[0], bB + ka);
        ldsm4(b[1], bB + ka + 16 * WSTR * 2);
        #pragma unroll
        for (int j = 0; j < 4; j++) {
            const uint32_t *bp = &b[j >> 1][2 * (j & 1)];
            mma_f16(acc[0][j], a[0], bp);
            mma_f16(acc[1][j], a[1], bp);
        }
    }
}

// cp.async load of a [128n x 64k] fp16 W tile, 256 threads
__device__ __forceinline__ void loadW(
    char *smem_w, const __half *W,
    int Kw, int nrow_base, int kofs, int tid)
{
    #pragma unroll
    for (int h = 0; h < 2; h++) {
        const int n = (tid >> 2) + h * 64;
        const int q = (tid & 3) * 16;
        const size_t g = (size_t)(nrow_base + n) * Kw + kofs + q;
        const uint32_t d = (uint32_t)__cvta_generic_to_shared(smem_w + (n * WSTR + q) * 2);
        cp16(d, W + g);
        cp16(d + 16, W + g + 8);
    }
}

// LN over 128 features (4 threads/row, thread owns cols c0..c0+31)
__device__ __forceinline__ void ln_row(float4 v[8], const float *lnw,
                                       const float *lnb, int c0)
{
    float s = 0.f, q = 0.f;
    #pragma unroll
    for (int i = 0; i < 8; i++) {
        s += v[i].x + v[i].y + v[i].z + v[i].w;
        q += v[i].x * v[i].x + v[i].y * v[i].y + v[i].z * v[i].z + v[i].w * v[i].w;
    }
    s += __shfl_xor_sync(0xffffffffu, s, 1);
    s += __shfl_xor_sync(0xffffffffu, s, 2);
    q += __shfl_xor_sync(0xffffffffu, q, 1);
    q += __shfl_xor_sync(0xffffffffu, q, 2);
    const float m  = s * (1.f / 128.f);
    const float rs = rsqrtf(q * (1.f / 128.f) - m * m + 1e-5f);
    #pragma unroll
    for (int i = 0; i < 8; i++) {
        const int gc = c0 + 4 * i;
        v[i].x = (v[i].x - m) * rs * lnw[gc + 0] + lnb[gc + 0];
        v[i].y = (v[i].y - m) * rs * lnw[gc + 1] + lnb[gc + 1];
        v[i].z = (v[i].z - m) * rs * lnw[gc + 2] + lnb[gc + 2];
        v[i].w = (v[i].w - m) * rs * lnw[gc + 3] + lnb[gc + 3];
    }
}
__device__ __forceinline__ void store_cvt(uint32_t *Au, const float4 v[8],
                                          int r, int c0)
{
    #pragma unroll
    for (int i = 0; i < 8; i++) {
        const int idx = (r * SSTR + c0 + 4 * i) >> 1;
        Au[idx]     = pack_h2(v[i].x, v[i].y);
        Au[idx + 1] = pack_h2(v[i].z, v[i].w);
    }
}

// direct fragment epilogue (R9 style)
__device__ __forceinline__ void epi_direct(
    float acc[2][4][4], int mw, int nw, int lane,
    int row0, int colbase, const float *bias, const float *resid,
    float *Y, int ldy, int R)
{
    #pragma unroll
    for (int mt = 0; mt < 2; mt++) {
        #pragma unroll
        for (int half = 0; half < 2; half++) {
            const int r = row0 + mw * 32 + mt * 16 + (lane >> 2) + half * 8;
            if (r < R) {
                #pragma unroll
                for (int j = 0; j < 4; j++) {
                    const int col = colbase + nw * 32 + j * 8 + 2 * (lane & 3);
                    float2 o;
                    o.x = acc[mt][j][half * 2 + 0];
                    o.y = acc[mt][j][half * 2 + 1];
                    if (bias) { o.x += bias[col]; o.y += bias[col + 1]; }
                    const size_t yb = (size_t)r * ldy + col;
                    if (resid) { o.x += resid[yb]; o.y += resid[yb + 1]; }
                    *reinterpret_cast<float2 *>(Y + yb) = o;
                }
            }
        }
    }
}

// ======================= generic pipelined GEMM (64-row tiles) =============
#define G_A  0
#define G_W  17408
#define G_SLOT 18432
#define G_TOT (G_W + 2 * G_SLOT)   // 54272

__global__ void __launch_bounds__(256, 3) tcgemm(
    const float *__restrict__ X, int ldx,
    const float *__restrict__ lnw, const float *__restrict__ lnb,
    const float *__restrict__ zdiv,
    const __half *__restrict__ W,
    int No, const float *__restrict__ bias, const float *__restrict__ resid,
    float *__restrict__ Y, int ldy, int R)
{
    extern __shared__ char smc[];
    char *Ac = smc + G_A;
    uint32_t *Au = reinterpret_cast<uint32_t *>(Ac);

    const int tid  = threadIdx.x;
    const int wid  = tid >> 5;
    const int lane = tid & 31;
    const int mw   = wid & 1;
    const int nw   = wid >> 1;
    const int row0 = blockIdx.x * 64;
    const bool do_ln = (lnw != nullptr);
    const int T = (No >> 7) * 2;

    loadW(smc + G_W,          W, 128, 0, 0, tid);  CP_COMMIT();
    loadW(smc + G_W + G_SLOT, W, 128, 0, 64, tid); CP_COMMIT();

    // ---- A: 64 rows, optional zdiv / LN, cvt to fp16 ----------------------
    {
        const int r  = tid >> 2;
        const int c0 = (tid & 3) * 32;
        const int grow = row0 + r;
        const bool valid = grow < R;
        float4 v[8];
        if (valid) {
            const float4 *xr = reinterpret_cast<const float4 *>(
                X + (size_t)grow * ldx + c0);
            #pragma unroll
            for (int i = 0; i < 8; i++) v[i] = xr[i];
        } else {
            #pragma unroll
            for (int i = 0; i < 8; i++) v[i] = make_float4(0.f, 0.f, 0.f, 0.f);
        }
        if (zdiv && valid) {
            const float rA = 1.f / (zdiv[(size_t)grow * 8 + (c0 >> 4)] + 1e-8f);
            const float rB = 1.f / (zdiv[(size_t)grow * 8 + (c0 >> 4) + 1] + 1e-8f);
            #pragma unroll
            for (int i = 0; i < 8; i++) {
                const float s = (i < 4) ? rA : rB;
                v[i].x *= s; v[i].y *= s; v[i].z *= s; v[i].w *= s;
            }
        }
        if (do_ln) ln_row(v, lnw, lnb, c0);
        store_cvt(Au, v, r, c0);
    }

    float acc[2][4][4];
    for (int t = 0; t < T; t++) {
        const int nt = t >> 1;
        if (!(t & 1)) {
            #pragma unroll
            for (int mt = 0; mt < 2; mt++)
                #pragma unroll
                for (int j = 0; j < 4; j++)
                    #pragma unroll
                    for (int q = 0; q < 4; q++) acc[mt][j][q] = 0.f;
        }
        if (t < T - 1) { CP_WAIT(1); } else { CP_WAIT(0); }
        __syncthreads();
        char *sh = smc + G_W + (t & 1) * G_SLOT;
        mma_tile(acc, Ac, (t & 1) * 64, sh, mw, nw, lane);
        __syncthreads();
        if (t + 2 < T) {
            loadW(sh, W, 128, ((t + 2) >> 1) * 128, ((t + 2) & 1) * 64, tid);
            CP_COMMIT();
        }
        if (t & 1)
            epi_direct(acc, mw, nw, lane, row0, nt * 128, bias, resid, Y, ldy, R);
    }
}

// ======================= fused LN2 + MLP chain (64-row) ====================
#define C_A  0
#define C_H  17408
#define C_W  34816
#define C_TOT 53248

__global__ void __launch_bounds__(256, 3) mlp_chain(
    float *__restrict__ Y,
    const float *__restrict__ lnw, const float *__restrict__ lnb,
    const __half *__restrict__ W1, const __half *__restrict__ W2,
    int R)
{
    extern __shared__ char smc[];
    char *Ac = smc + C_A;  char *Hc = smc + C_H;
    uint32_t *Au = reinterpret_cast<uint32_t *>(Ac);
    uint32_t *Hu = reinterpret_cast<uint32_t *>(Hc);
    char *wc = smc + C_W;

    const int tid  = threadIdx.x;
    const int wid  = tid >> 5;
    const int lane = tid & 31;
    const int mw   = wid & 1;
    const int nw   = wid >> 1;
    const int row0 = blockIdx.x * 64;

    loadW(wc, W1, 128, 0, 0, tid); CP_COMMIT();

    // ---- A: 64 rows + LN2, cvt -------------------------------------------
    {
        const int r  = tid >> 2;
        const int c0 = (tid & 3) * 32;
        const int grow = row0 + r;
        const bool valid = grow < R;
        float4 v[8];
        if (valid) {
            const float4 *xr = reinterpret_cast<const float4 *>(
                Y + (size_t)grow * 128 + c0);
            #pragma unroll
            for (int i = 0; i < 8; i++) v[i] = xr[i];
        } else {
            #pragma unroll
            for (int i = 0; i < 8; i++) v[i] = make_float4(0.f, 0.f, 0.f, 0.f);
        }
        ln_row(v, lnw, lnb, c0);
        store_cvt(Au, v, r, c0);
    }

    float acc1[2][4][4], acc2[2][4][4];
    #pragma unroll
    for (int mt = 0; mt < 2; mt++)
        #pragma unroll
        for (int j = 0; j < 4; j++)
            #pragma unroll
            for (int q = 0; q < 4; q++) acc2[mt][j][q] = 0.f;

    #pragma unroll
    for (int h = 0; h < 2; h++) {
        #pragma unroll
        for (int mt = 0; mt < 2; mt++)
            #pragma unroll
            for (int j = 0; j < 4; j++)
                #pragma unroll
                for (int q = 0; q < 4; q++) acc1[mt][j][q] = 0.f;

        if (h == 1) { loadW(wc, W1, 128, 128, 0, tid); CP_COMMIT(); }
        CP_WAIT(0); __syncthreads();
        mma_tile(acc1, Ac, 0, wc, mw, nw, lane);
        __syncthreads();
        loadW(wc, W1, 128, h * 128, 64, tid); CP_COMMIT();
        CP_WAIT(0); __syncthreads();
        mma_tile(acc1, Ac, 64, wc, mw, nw, lane);

        // silu -> H (smem only, fragment layout)
        #pragma unroll
        for (int mt = 0; mt < 2; mt++)
            #pragma unroll
            for (int qh = 0; qh < 2; qh++)
                #pragma unroll
                for (int j = 0; j < 4; j++) {
                    const int rl = mw * 32 + mt * 16 + (lane >> 2) + qh * 8;
                    const int cl = nw * 32 + j * 8 + 2 * (lane & 3);
                    float x = acc1[mt][j][qh * 2 + 0];
                    float y = acc1[mt][j][qh * 2 + 1];
                    x = x / (1.f + __expf(-x));
                    y = y / (1.f + __expf(-y));
                    Hu[(rl * SSTR + cl) >> 1] = pack_h2(x, y);
                }
        __syncthreads();

        // acc2 += H @ W2[:, h*128 : h*128+128]
        loadW(wc, W2, 256, 0, h * 128, tid); CP_COMMIT();
        CP_WAIT(0); __syncthreads();
        mma_tile(acc2, Hc, 0, wc, mw, nw, lane);
        __syncthreads();
        loadW(wc, W2, 256, 0, h * 128 + 64, tid); CP_COMMIT();
        CP_WAIT(0); __syncthreads();
        mma_tile(acc2, Hc, 64, wc, mw, nw, lane);
        __syncthreads();
    }

    epi_direct(acc2, mw, nw, lane, row0, 0, nullptr, Y, Y, 128, R);
}

// ============ fused edge: LN1e + We proj + attention + Wo_e ================
// smem: Ae fp16 | 2 W slots | P staging fp32 (64 x 132)
#define F_A  0
#define F_W0 17408
#define F_W1 (F_W0 + 18432)
#define F_P  (F_W1 + 18432)
#define PST  132
#define F_TOT (F_P + 64 * PST * 4)     // 88064

__global__ void __launch_bounds__(256, 2) edge_fused(
    const float *__restrict__ edge,
    const float *__restrict__ lnw, const float *__restrict__ lnb,
    const float *__restrict__ QKV,
    const int *__restrict__ src, const int *__restrict__ dst,
    const __half *__restrict__ We, const float *__restrict__ be,
    const __half *__restrict__ Wo, const float *__restrict__ bo,
    float *__restrict__ wV, float *__restrict__ z,
    float *__restrict__ Y)
{
    extern __shared__ char smc[];
    char *Ac = smc + F_A;
    uint32_t *Au = reinterpret_cast<uint32_t *>(Ac);
    char *w0 = smc + F_W0;
    char *w1 = smc + F_W1;
    float *Pst = reinterpret_cast<float *>(smc + F_P);

    const int tid  = threadIdx.x;
    const int wid  = tid >> 5;
    const int lane = tid & 31;
    const int mw   = wid & 1;
    const int nw   = wid >> 1;
    const int row0 = blockIdx.x * 64;      // EE % 64 == 0

    loadW(w0, We, 128, 0, 0, tid);  CP_COMMIT();
    loadW(w1, We, 128, 0, 64, tid); CP_COMMIT();

    // ---- A phase 1: edge rows + LN1e -> fp16 smem -------------------------
    {
        const int r  = tid >> 2;
        const int c0 = (tid & 3) * 32;
        const float4 *xr = reinterpret_cast<const float4 *>(
            edge + (size_t)(row0 + r) * 128 + c0);
        float4 v[8];
        #pragma unroll
        for (int i = 0; i < 8; i++) v[i] = xr[i];
        ln_row(v, lnw, lnb, c0);
        store_cvt(Au, v, r, c0);
    }

    // ---- GEMM1: P = Ae @ We -----------------------------------------------
    float acc[2][4][4];
    #pragma unroll
    for (int mt = 0; mt < 2; mt++)
        #pragma unroll
        for (int j = 0; j < 4; j++)
            #pragma unroll
            for (int q = 0; q < 4; q++) acc[mt][j][q] = 0.f;

    CP_WAIT(1); __syncthreads();
    mma_tile(acc, Ac, 0, w0, mw, nw, lane);
    __syncthreads();
    loadW(w0, Wo, 128, 0, 0, tid); CP_COMMIT();
    CP_WAIT(1); __syncthreads();
    mma_tile(acc, Ac, 64, w1, mw, nw, lane);
    __syncthreads();                       // all Ae reads done
    loadW(w1, Wo, 128, 0, 64, tid); CP_COMMIT();

    // ---- stage P fragments -> Pst -----------------------------------------
    #pragma unroll
    for (int mt = 0; mt < 2; mt++)
        #pragma unroll
        for (int half = 0; half < 2; half++)
            #pragma unroll
            for (int j = 0; j < 4; j++) {
                const int rl = mw * 32 + mt * 16 + half * 8 + (lane >> 2);
                const int cl = nw * 32 + j * 8 + 2 * (lane & 3);
                float2 o;
                o.x = acc[mt][j][half * 2 + 0];
                o.y = acc[mt][j][half * 2 + 1];
                *reinterpret_cast<float2 *>(Pst + rl * PST + cl) = o;
            }
    __syncthreads();

    // ---- attention phase: P from smem, gathers from QKV, eo -> Ae ---------
    {
        const int r  = tid >> 2;
        const int c0 = (tid & 3) * 32;
        const int e  = row0 + r;
        const int s = src[e];
        const int d = dst[e];
        const float *kr = QKV + (size_t)s * 384 + 128 + c0;
        const float *qr = QKV + (size_t)d * 384 + c0;
        const float *vr = QKV + (size_t)s * 384 + 256 + c0;
        const float *pp = Pst + r * PST + c0;

        float4 eo[8];
        float sA = 0.f, sB = 0.f;
        #pragma unroll
        for (int i = 0; i < 8; i++) {
            const float4 kv = *reinterpret_cast<const float4 *>(kr + 4 * i);
            const float4 qv = *reinterpret_cast<const float4 *>(qr + 4 * i);
            const float4 bv = *reinterpret_cast<const float4 *>(be + c0 + 4 * i);
            float4 pv = *reinterpret_cast<const float4 *>(pp + 4 * i);
            pv.x += bv.x; pv.y += bv.y; pv.z += bv.z; pv.w += bv.w;
            float4 t;
            t.x = CLIP5(kv.x * qv.x * 0.25f) * pv.x;
            t.y = CLIP5(kv.y * qv.y * 0.25f) * pv.y;
            t.z = CLIP5(kv.z * qv.z * 0.25f) * pv.z;
            t.w = CLIP5(kv.w * qv.w * 0.25f) * pv.w;
            eo[i] = t;
            const float ts = t.x + t.y + t.z + t.w;
            if (i < 4) sA += ts; else sB += ts;
        }
        const float wA = __expf(CLIP5(sA));
        const float wB = __expf(CLIP5(sB));
        float *wvp = wV + (size_t)d * 128 + c0;
        #pragma unroll
        for (int i = 0; i < 8; i++) {
            const float w = (i < 4) ? wA : wB;
            const float4 vv = *reinterpret_cast<const float4 *>(vr + 4 * i);
            atomicAdd(wvp + 4 * i + 0, vv.x * w);
            atomicAdd(wvp + 4 * i + 1, vv.y * w);
            atomicAdd(wvp + 4 * i + 2, vv.z * w);
            atomicAdd(wvp + 4 * i + 3, vv.w * w);
        }
        atomicAdd(z + (size_t)d * 8 + (c0 >> 4),     wA);
        atomicAdd(z + (size_t)d * 8 + (c0 >> 4) + 1, wB);

        store_cvt(Au, eo, r, c0);          // overwrite Ae with e_out
    }

    // ---- GEMM2: out = eo @ Wo_e -------------------------------------------
    #pragma unroll
    for (int mt = 0; mt < 2; mt++)
        #pragma unroll
        for (int j = 0; j < 4; j++)
            #pragma unroll
            for (int q = 0; q < 4; q++) acc[mt][j][q] = 0.f;

    CP_WAIT(1); __syncthreads();
    mma_tile(acc, Ac, 0, w0, mw, nw, lane);
    CP_WAIT(0); __syncthreads();
    mma_tile(acc, Ac, 64, w1, mw, nw, lane);

    epi_direct(acc, mw, nw, lane, row0, 0, bo, edge, Y, 128, EE);
}

// --------------- single-launch weight convert/transpose --------------------
struct WDesc { const float *W; int K; int No; int ofs; int start; };
struct WPack { WDesc d[10]; int total; };

__global__ void split_all(WPack p, __half *__restrict__ out)
{
    int i = blockIdx.x * 256 + threadIdx.x;
    if (i >= p.total) return;
    #pragma unroll
    for (int m = 0; m < 10; m++) {
        const WDesc &d = p.d[m];
        const int sz = d.K * d.No;
        if (i < d.start + sz) {
            const int il = i - d.start;
            const int k = il / d.No;
            const int n = il - k * d.No;
            out[(size_t)d.ofs + (size_t)n * d.K + k] = __float2half(d.W[il]);
            return;
        }
    }
}

__global__ void pack_bias(const float *__restrict__ a, const float *__restrict__ b,
                          const float *__restrict__ c, float *__restrict__ o)
{
    const int i = threadIdx.x;
    if (i < 128) { o[i] = a[i]; o[128 + i] = b[i]; o[256 + i] = c[i]; }
}

// ---------------------------------------------------------------------------
extern "C" void kernel_launch(void *const *d_in, const int *in_sizes, int n_in,
                              void *d_out, int out_size)
{
    const float *node   = (const float *)d_in[0];
    const float *edge   = (const float *)d_in[1];
    const int   *src    = (const int *)d_in[2];
    const int   *dst    = (const int *)d_in[3];
    const float *ln1n_w = (const float *)d_in[4];
    const float *ln1n_b = (const float *)d_in[5];
    const float *ln1e_w = (const float *)d_in[6];
    const float *ln1e_b = (const float *)d_in[7];
    const float *ln2n_w = (const float *)d_in[8];
    const float *ln2n_b = (const float *)d_in[9];
    const float *ln2e_w = (const float *)d_in[10];
    const float *ln2e_b = (const float *)d_in[11];
    const float *Wq = (const float *)d_in[12];  const float *bq = (const float *)d_in[13];
    const float *Wk = (const float *)d_in[14];  const float *bk = (const float *)d_in[15];
    const float *Wv = (const float *)d_in[16];  const float *bv = (const float *)d_in[17];
    const float *We = (const float *)d_in[18];  const float *be = (const float *)d_in[19];
    const float *Wo_n = (const float *)d_in[20]; const float *bo_n = (const float *)d_in[21];
    const float *Wo_e = (const float *)d_in[22]; const float *bo_e = (const float *)d_in[23];
    const float *w1n = (const float *)d_in[24];
    const float *w2n = (const float *)d_in[25];
    const float *w1e = (const float *)d_in[26];
    const float *w2e = (const float *)d_in[27];

    float *outh = (float *)d_out;
    float *oute = outh + (size_t)NN * DD;

    float *QKVp, *wVp, *zp, *bqkv;
    __half *WFp;
    cudaGetSymbolAddress((void **)&QKVp, g_QKV);
    cudaGetSymbolAddress((void **)&wVp, g_wV);
    cudaGetSymbolAddress((void **)&zp,  g_z);
    cudaGetSymbolAddress((void **)&bqkv, g_bqkv);
    cudaGetSymbolAddress((void **)&WFp, g_WF);

    cudaFuncSetAttribute(tcgemm,     cudaFuncAttributeMaxDynamicSharedMemorySize, G_TOT);
    cudaFuncSetAttribute(mlp_chain,  cudaFuncAttributeMaxDynamicSharedMemorySize, C_TOT);
    cudaFuncSetAttribute(edge_fused, cudaFuncAttributeMaxDynamicSharedMemorySize, F_TOT);

    WPack p;
    int st = 0;
    auto add = [&](int m, const float *W, int K, int No, int ofs) {
        p.d[m] = {W, K, No, ofs, st};
        st += K * No;
    };
    add(0, Wq, 128, 128, OF_QKV);
    add(1, Wk, 128, 128, OF_QKV + 16384);
    add(2, Wv, 128, 128, OF_QKV + 32768);
    add(3, We, 128, 128, OF_WE);
    add(4, Wo_n, 128, 128, OF_WON);
    add(5, Wo_e, 128, 128, OF_WOE);
    add(6, w1n, 128, 256, OF_W1N);
    add(7, w2n, 256, 128, OF_W2N);
    add(8, w1e, 128, 256, OF_W1E);
    add(9, w2e, 256, 128, OF_W2E);
    p.total = st;
    split_all<<<(st + 255) / 256, 256>>>(p, WFp);
    pack_bias<<<1, 128>>>(bq, bk, bv, bqkv);

    cudaMemsetAsync(wVp, 0, (size_t)NN * DD * sizeof(float), 0);
    cudaMemsetAsync(zp,  0, (size_t)NN * HH * sizeof(float), 0);

    const int GN = (NN + 63) / 64;
    const int GE = EE / 64;

    // LN1 + fused QKV projection (No=384) -> QKV table
    tcgemm<<<GN, 256, G_TOT>>>(node, 128, ln1n_w, ln1n_b, nullptr,
                               WFp + OF_QKV, 384, bqkv, nullptr,
                               QKVp, 384, NN);

    // fused: LN1e + We proj + attention + Wo_e + resid -> oute (+ wV, z)
    edge_fused<<<GE, 256, F_TOT>>>(edge, ln1e_w, ln1e_b, QKVp, src, dst,
                                   WFp + OF_WE, be, WFp + OF_WOE, bo_e,
                                   wVp, zp, oute);

    // node output projection: A = wV / z, + resid -> outh
    tcgemm<<<GN, 256, G_TOT>>>(wVp, 128, nullptr, nullptr, zp,
                               WFp + OF_WON, 128, bo_n, node,
                               outh, 128, NN);

    // fused LN2 + MLP + resid, in place
    mlp_chain<<<GN, 256, C_TOT>>>(outh, ln2n_w, ln2n_b,
                                  WFp + OF_W1N, WFp + OF_W2N, NN);
    mlp_chain<<<GE, 256, C_TOT>>>(oute, ln2e_w, ln2e_b,
                                  WFp + OF_W1E, WFp + OF_W2E, EE);
}

// round 16
// speedup vs baseline: 1.0826x; 1.0152x over previous
#include <cuda_runtime.h>
#include <cuda_fp16.h>
#include <cstdint>

#define NN 50000
#define EE 800000
#define DD 128
#define HH 8

// ---------------- scratch (static device arrays; no allocation) ------------
__device__ float g_QKV[(size_t)NN * 384];
__device__ float g_wV[(size_t)NN * DD];
__device__ float g_z [(size_t)NN * HH];
__device__ float g_bqkv[384];

// fp16 weights, [n][k] layout, packed
#define OF_QKV  0
#define OF_WE   49152
#define OF_WON  65536
#define OF_WOE  81920
#define OF_W1N  98304
#define OF_W2N  131072
#define OF_W1E  163840
#define OF_W2E  196608
#define W_TOT   229376
__device__ __half g_WF[W_TOT];

// =================== helpers ===============================================
__device__ __forceinline__ void mma_f16(float *c, const uint32_t *a,
                                        const uint32_t *b) {
    asm volatile(
        "mma.sync.aligned.m16n8k16.row.col.f32.f16.f16.f32 "
        "{%0,%1,%2,%3}, {%4,%5,%6,%7}, {%8,%9}, {%0,%1,%2,%3};"
        : "+f"(c[0]), "+f"(c[1]), "+f"(c[2]), "+f"(c[3])
        : "r"(a[0]), "r"(a[1]), "r"(a[2]), "r"(a[3]), "r"(b[0]), "r"(b[1]));
}
__device__ __forceinline__ void ldsm4(uint32_t *r, uint32_t addr) {
    asm volatile("ldmatrix.sync.aligned.m8n8.x4.shared.b16 {%0,%1,%2,%3}, [%4];"
                 : "=r"(r[0]), "=r"(r[1]), "=r"(r[2]), "=r"(r[3]) : "r"(addr));
}
__device__ __forceinline__ uint32_t pack_h2(float x, float y) {
    __half2 t = __floats2half2_rn(x, y);
    return *reinterpret_cast<uint32_t *>(&t);
}
__device__ __forceinline__ void cp16(uint32_t saddr, const void *g) {
    asm volatile("cp.async.cg.shared.global [%0], [%1], 16;"
                 :: "r"(saddr), "l"(g));
}
#define CP_COMMIT() asm volatile("cp.async.commit_group;" ::: "memory")
#define CP_WAIT(n)  asm volatile("cp.async.wait_group %0;" :: "n"(n) : "memory")
#define CLIP5(x) fminf(fmaxf((x), -5.f), 5.f)

#define SSTR 136     // A/H smem stride (fp16)
#define WSTR 72      // W tile stride (fp16)
#define PST  132     // Pst stride (fp32)

#define ZERO_ACC(a) do {                                                     \
    _Pragma("unroll")                                                        \
    for (int _mt = 0; _mt < 2; _mt++)                                        \
        _Pragma("unroll")                                                    \
        for (int _j = 0; _j < 4; _j++)                                       \
            _Pragma("unroll")                                                \
            for (int _q = 0; _q < 4; _q++) (a)[_mt][_j][_q] = 0.f;           \
} while (0)

// one 64x128(A rows) x [128n x 64k](B) fp16 MMA pass:
// 8 warps as 2(M: mw) x 4(N: nw), each warp 32x32.
__device__ __forceinline__ void mma_tile(
    float acc[2][4][4],
    const char *A, int kbase, const char *B,
    int mw, int nw, int lane)
{
    const uint32_t aoff = (uint32_t)(((mw * 32 + (lane & 15)) * SSTR +
                                      kbase + (lane >> 4) * 8) * 2);
    const uint32_t boff = (uint32_t)(((nw * 32 + ((lane >> 4) & 1) * 8 + (lane & 7)) * WSTR +
                                      ((lane >> 3) & 1) * 8) * 2);
    const uint32_t aB = (uint32_t)__cvta_generic_to_shared(A) + aoff;
    const uint32_t bB = (uint32_t)__cvta_generic_to_shared(B) + boff;

    #pragma unroll
    for (int kk = 0; kk < 4; kk++) {
        const uint32_t ka = kk * 32;
        uint32_t a[2][4], b[2][4];
        ldsm4(a[0], aB + ka);
        ldsm4(a[1], aB + ka + 16 * SSTR * 2);
        ldsm4(b[0], bB + ka);
        ldsm4(b[1], bB + ka + 16 * WSTR * 2);
        #pragma unroll
        for (int j = 0; j < 4; j++) {
            const uint32_t *bp = &b[j >> 1][2 * (j & 1)];
            mma_f16(acc[0][j], a[0], bp);
            mma_f16(acc[1][j], a[1], bp);
        }
    }
}

// cp.async load of a [128n x 64k] fp16 W tile, 256 threads
__device__ __forceinline__ void loadW(
    char *smem_w, const __half *W,
    int Kw, int nrow_base, int kofs, int tid)
{
    #pragma unroll
    for (int h = 0; h < 2; h++) {
        const int n = (tid >> 2) + h * 64;
        const int q = (tid & 3) * 16;
        const size_t g = (size_t)(nrow_base + n) * Kw + kofs + q;
        const uint32_t d = (uint32_t)__cvta_generic_to_shared(smem_w + (n * WSTR + q) * 2);
        cp16(d, W + g);
        cp16(d + 16, W + g + 8);
    }
}

// LN over 128 features (4 threads/row, thread owns cols c0..c0+31)
__device__ __forceinline__ void ln_row(float4 v[8], const float *lnw,
                                       const float *lnb, int c0)
{
    float s = 0.f, q = 0.f;
    #pragma unroll
    for (int i = 0; i < 8; i++) {
        s += v[i].x + v[i].y + v[i].z + v[i].w;
        q += v[i].x * v[i].x + v[i].y * v[i].y + v[i].z * v[i].z + v[i].w * v[i].w;
    }
    s += __shfl_xor_sync(0xffffffffu, s, 1);
    s += __shfl_xor_sync(0xffffffffu, s, 2);
    q += __shfl_xor_sync(0xffffffffu, q, 1);
    q += __shfl_xor_sync(0xffffffffu, q, 2);
    const float m  = s * (1.f / 128.f);
    const float rs = rsqrtf(q * (1.f / 128.f) - m * m + 1e-5f);
    #pragma unroll
    for (int i = 0; i < 8; i++) {
        const int gc = c0 + 4 * i;
        v[i].x = (v[i].x - m) * rs * lnw[gc + 0] + lnb[gc + 0];
        v[i].y = (v[i].y - m) * rs * lnw[gc + 1] + lnb[gc + 1];
        v[i].z = (v[i].z - m) * rs * lnw[gc + 2] + lnb[gc + 2];
        v[i].w = (v[i].w - m) * rs * lnw[gc + 3] + lnb[gc + 3];
    }
}
__device__ __forceinline__ void store_cvt(uint32_t *Au, const float4 v[8],
                                          int r, int c0)
{
    #pragma unroll
    for (int i = 0; i < 8; i++) {
        const int idx = (r * SSTR + c0 + 4 * i) >> 1;
        Au[idx]     = pack_h2(v[i].x, v[i].y);
        Au[idx + 1] = pack_h2(v[i].z, v[i].w);
    }
}

// direct fragment epilogue
__device__ __forceinline__ void epi_direct(
    float acc[2][4][4], int mw, int nw, int lane,
    int row0, int colbase, const float *bias, const float *resid,
    float *Y, int ldy, int R)
{
    #pragma unroll
    for (int mt = 0; mt < 2; mt++) {
        #pragma unroll
        for (int half = 0; half < 2; half++) {
            const int r = row0 + mw * 32 + mt * 16 + (lane >> 2) + half * 8;
            if (r < R) {
                #pragma unroll
                for (int j = 0; j < 4; j++) {
                    const int col = colbase + nw * 32 + j * 8 + 2 * (lane & 3);
                    float2 o;
                    o.x = acc[mt][j][half * 2 + 0];
                    o.y = acc[mt][j][half * 2 + 1];
                    if (bias) { o.x += bias[col]; o.y += bias[col + 1]; }
                    const size_t yb = (size_t)r * ldy + col;
                    if (resid) { o.x += resid[yb]; o.y += resid[yb + 1]; }
                    *reinterpret_cast<float2 *>(Y + yb) = o;
                }
            }
        }
    }
}

// stage fragments into Pst (optional bias)
__device__ __forceinline__ void stage_pst(
    float acc[2][4][4], float *Pst, const float *bias,
    int mw, int nw, int lane)
{
    #pragma unroll
    for (int mt = 0; mt < 2; mt++)
        #pragma unroll
        for (int half = 0; half < 2; half++)
            #pragma unroll
            for (int j = 0; j < 4; j++) {
                const int rl = mw * 32 + mt * 16 + half * 8 + (lane >> 2);
                const int cl = nw * 32 + j * 8 + 2 * (lane & 3);
                float2 o;
                o.x = acc[mt][j][half * 2 + 0];
                o.y = acc[mt][j][half * 2 + 1];
                if (bias) { o.x += bias[cl]; o.y += bias[cl + 1]; }
                *reinterpret_cast<float2 *>(Pst + rl * PST + cl) = o;
            }
}

// ---- shared smem layout for mega kernels ----------------------------------
#define M_A   0
#define M_H   17408
#define M_P   34816
#define M_W0  (M_P + 64 * PST * 4)       // 68608
#define M_W1  (M_W0 + 18432)             // 87040
#define M_TOT (M_W1 + 18432)             // 105472

// ---- MLP tail: Pst holds y=proj+bias; add residG, LN, 2-layer MLP, +y -----
// On entry: exactly 2 cp groups pending: W1 tile (0,k0) in w0, (0,k64) in w1.
__device__ __forceinline__ void mlp_tail(
    char *Ac, char *Hc, float *Pst, char *w0, char *w1,
    const float *lnw, const float *lnb,
    const __half *W1, const __half *W2,
    const float *residG, float *Y, int row0, int R,
    int tid, int lane, int mw, int nw)
{
    uint32_t *Au = reinterpret_cast<uint32_t *>(Ac);
    uint32_t *Hu = reinterpret_cast<uint32_t *>(Hc);

    __syncthreads();                      // Pst staged
    // step1: Pst += residG (coalesced), keep sum in Pst, LN -> A
    {
        const int r  = tid >> 2;
        const int c0 = (tid & 3) * 32;
        const int grow = row0 + r;
        float4 v[8];
        if (grow < R) {
            #pragma unroll
            for (int i = 0; i < 8; i++) {
                float4 pv = *reinterpret_cast<float4 *>(Pst + r * PST + c0 + 4 * i);
                const float4 rv = *reinterpret_cast<const float4 *>(
                    residG + (size_t)grow * 128 + c0 + 4 * i);
                pv.x += rv.x; pv.y += rv.y; pv.z += rv.z; pv.w += rv.w;
                *reinterpret_cast<float4 *>(Pst + r * PST + c0 + 4 * i) = pv;
                v[i] = pv;
            }
        } else {
            #pragma unroll
            for (int i = 0; i < 8; i++) v[i] = make_float4(0.f, 0.f, 0.f, 0.f);
        }
        ln_row(v, lnw, lnb, c0);
        store_cvt(Au, v, r, c0);
    }

    float acc1[2][4][4], acc2[2][4][4];
    ZERO_ACC(acc2);

    auto silu_to_H = [&](float a[2][4][4]) {
        #pragma unroll
        for (int mt = 0; mt < 2; mt++)
            #pragma unroll
            for (int qh = 0; qh < 2; qh++)
                #pragma unroll
                for (int j = 0; j < 4; j++) {
                    const int rl = mw * 32 + mt * 16 + (lane >> 2) + qh * 8;
                    const int cl = nw * 32 + j * 8 + 2 * (lane & 3);
                    float x = a[mt][j][qh * 2 + 0];
                    float y = a[mt][j][qh * 2 + 1];
                    x = x / (1.f + __expf(-x));
                    y = y / (1.f + __expf(-y));
                    Hu[(rl * SSTR + cl) >> 1] = pack_h2(x, y);
                }
    };

    // ---- half 0 ----
    ZERO_ACC(acc1);
    CP_WAIT(1); __syncthreads();
    mma_tile(acc1, Ac, 0, w0, mw, nw, lane);
    __syncthreads();
    loadW(w0, W2, 256, 0, 0, tid); CP_COMMIT();
    CP_WAIT(1); __syncthreads();
    mma_tile(acc1, Ac, 64, w1, mw, nw, lane);
    __syncthreads();
    loadW(w1, W2, 256, 0, 64, tid); CP_COMMIT();
    silu_to_H(acc1);
    CP_WAIT(1); __syncthreads();
    mma_tile(acc2, Hc, 0, w0, mw, nw, lane);
    __syncthreads();
    loadW(w0, W1, 128, 128, 0, tid); CP_COMMIT();
    CP_WAIT(1); __syncthreads();
    mma_tile(acc2, Hc, 64, w1, mw, nw, lane);
    __syncthreads();
    loadW(w1, W1, 128, 128, 64, tid); CP_COMMIT();

    // ---- half 1 ----
    ZERO_ACC(acc1);
    CP_WAIT(1); __syncthreads();
    mma_tile(acc1, Ac, 0, w0, mw, nw, lane);
    __syncthreads();
    loadW(w0, W2, 256, 0, 128, tid); CP_COMMIT();
    CP_WAIT(1); __syncthreads();
    mma_tile(acc1, Ac, 64, w1, mw, nw, lane);
    __syncthreads();
    loadW(w1, W2, 256, 0, 192, tid); CP_COMMIT();
    silu_to_H(acc1);
    CP_WAIT(1); __syncthreads();
    mma_tile(acc2, Hc, 0, w0, mw, nw, lane);
    CP_WAIT(0); __syncthreads();
    mma_tile(acc2, Hc, 64, w1, mw, nw, lane);

    // ---- epilogue: out = acc2 + Pst ----
    #pragma unroll
    for (int mt = 0; mt < 2; mt++) {
        #pragma unroll
        for (int half = 0; half < 2; half++) {
            const int rl = mw * 32 + mt * 16 + (lane >> 2) + half * 8;
            const int r  = row0 + rl;
            if (r < R) {
                #pragma unroll
                for (int j = 0; j < 4; j++) {
                    const int cl = nw * 32 + j * 8 + 2 * (lane & 3);
                    float2 o;
                    o.x = acc2[mt][j][half * 2 + 0] + Pst[rl * PST + cl];
                    o.y = acc2[mt][j][half * 2 + 1] + Pst[rl * PST + cl + 1];
                    *reinterpret_cast<float2 *>(Y + (size_t)r * 128 + cl) = o;
                }
            }
        }
    }
}

// ======================= generic pipelined GEMM (QKV projection) ===========
#define G_A  0
#define G_W  17408
#define G_SLOT 18432
#define G_TOT (G_W + 2 * G_SLOT)   // 54272

__global__ void __launch_bounds__(256, 3) tcgemm(
    const float *__restrict__ X, int ldx,
    const float *__restrict__ lnw, const float *__restrict__ lnb,
    const __half *__restrict__ W,
    int No, const float *__restrict__ bias,
    float *__restrict__ Y, int ldy, int R)
{
    extern __shared__ char smc[];
    char *Ac = smc + G_A;
    uint32_t *Au = reinterpret_cast<uint32_t *>(Ac);

    const int tid  = threadIdx.x;
    const int wid  = tid >> 5;
    const int lane = tid & 31;
    const int mw   = wid & 1;
    const int nw   = wid >> 1;
    const int row0 = blockIdx.x * 64;
    const int T = (No >> 7) * 2;

    loadW(smc + G_W,          W, 128, 0, 0, tid);  CP_COMMIT();
    loadW(smc + G_W + G_SLOT, W, 128, 0, 64, tid); CP_COMMIT();

    {
        const int r  = tid >> 2;
        const int c0 = (tid & 3) * 32;
        const int grow = row0 + r;
        const bool valid = grow < R;
        float4 v[8];
        if (valid) {
            const float4 *xr = reinterpret_cast<const float4 *>(
                X + (size_t)grow * ldx + c0);
            #pragma unroll
            for (int i = 0; i < 8; i++) v[i] = xr[i];
        } else {
            #pragma unroll
            for (int i = 0; i < 8; i++) v[i] = make_float4(0.f, 0.f, 0.f, 0.f);
        }
        ln_row(v, lnw, lnb, c0);
        store_cvt(Au, v, r, c0);
    }

    float acc[2][4][4];
    for (int t = 0; t < T; t++) {
        const int nt = t >> 1;
        if (!(t & 1)) ZERO_ACC(acc);
        if (t < T - 1) { CP_WAIT(1); } else { CP_WAIT(0); }
        __syncthreads();
        char *sh = smc + G_W + (t & 1) * G_SLOT;
        mma_tile(acc, Ac, (t & 1) * 64, sh, mw, nw, lane);
        __syncthreads();
        if (t + 2 < T) {
            loadW(sh, W, 128, ((t + 2) >> 1) * 128, ((t + 2) & 1) * 64, tid);
            CP_COMMIT();
        }
        if (t & 1)
            epi_direct(acc, mw, nw, lane, row0, nt * 128, bias, nullptr, Y, ldy, R);
    }
}

// ============ edge megakernel: LN1e+We+attention+Wo_e+LN2e+MLP =============
__global__ void __launch_bounds__(256, 2) edge_mega(
    const float *__restrict__ edge,
    const float *__restrict__ ln1w, const float *__restrict__ ln1b,
    const float *__restrict__ QKV,
    const int *__restrict__ src, const int *__restrict__ dst,
    const __half *__restrict__ We, const float *__restrict__ be,
    const __half *__restrict__ Wo, const float *__restrict__ bo,
    const float *__restrict__ ln2w, const float *__restrict__ ln2b,
    const __half *__restrict__ W1, const __half *__restrict__ W2,
    float *__restrict__ wV, float *__restrict__ z,
    float *__restrict__ Y)
{
    extern __shared__ char smc[];
    char *Ac = smc + M_A;
    char *Hc = smc + M_H;
    uint32_t *Au = reinterpret_cast<uint32_t *>(Ac);
    float *Pst = reinterpret_cast<float *>(smc + M_P);
    char *w0 = smc + M_W0;
    char *w1 = smc + M_W1;

    const int tid  = threadIdx.x;
    const int wid  = tid >> 5;
    const int lane = tid & 31;
    const int mw   = wid & 1;
    const int nw   = wid >> 1;
    const int row0 = blockIdx.x * 64;      // EE % 64 == 0

    loadW(w0, We, 128, 0, 0, tid);  CP_COMMIT();
    loadW(w1, We, 128, 0, 64, tid); CP_COMMIT();

    // ---- A: edge rows + LN1e -> fp16 smem ---------------------------------
    {
        const int r  = tid >> 2;
        const int c0 = (tid & 3) * 32;
        const float4 *xr = reinterpret_cast<const float4 *>(
            edge + (size_t)(row0 + r) * 128 + c0);
        float4 v[8];
        #pragma unroll
        for (int i = 0; i < 8; i++) v[i] = xr[i];
        ln_row(v, ln1w, ln1b, c0);
        store_cvt(Au, v, r, c0);
    }

    // ---- GEMM1: P = Ae @ We ----
    float acc[2][4][4];
    ZERO_ACC(acc);
    CP_WAIT(1); __syncthreads();
    mma_tile(acc, Ac, 0, w0, mw, nw, lane);
    __syncthreads();
    loadW(w0, Wo, 128, 0, 0, tid); CP_COMMIT();
    CP_WAIT(1); __syncthreads();
    mma_tile(acc, Ac, 64, w1, mw, nw, lane);
    __syncthreads();
    loadW(w1, Wo, 128, 0, 64, tid); CP_COMMIT();

    stage_pst(acc, Pst, nullptr, mw, nw, lane);
    __syncthreads();

    // ---- attention: P from Pst (+be), gathers from QKV, eo -> A -----------
    {
        const int r  = tid >> 2;
        const int c0 = (tid & 3) * 32;
        const int e  = row0 + r;
        const int s = src[e];
        const int d = dst[e];
        const float *kr = QKV + (size_t)s * 384 + 128 + c0;
        const float *qr = QKV + (size_t)d * 384 + c0;
        const float *vr = QKV + (size_t)s * 384 + 256 + c0;
        const float *pp = Pst + r * PST + c0;

        float4 eo[8];
        float sA = 0.f, sB = 0.f;
        #pragma unroll
        for (int i = 0; i < 8; i++) {
            const float4 kv = *reinterpret_cast<const float4 *>(kr + 4 * i);
            const float4 qv = *reinterpret_cast<const float4 *>(qr + 4 * i);
            const float4 bv = *reinterpret_cast<const float4 *>(be + c0 + 4 * i);
            float4 pv = *reinterpret_cast<const float4 *>(pp + 4 * i);
            pv.x += bv.x; pv.y += bv.y; pv.z += bv.z; pv.w += bv.w;
            float4 t;
            t.x = CLIP5(kv.x * qv.x * 0.25f) * pv.x;
            t.y = CLIP5(kv.y * qv.y * 0.25f) * pv.y;
            t.z = CLIP5(kv.z * qv.z * 0.25f) * pv.z;
            t.w = CLIP5(kv.w * qv.w * 0.25f) * pv.w;
            eo[i] = t;
            const float ts = t.x + t.y + t.z + t.w;
            if (i < 4) sA += ts; else sB += ts;
        }
        const float wA = __expf(CLIP5(sA));
        const float wB = __expf(CLIP5(sB));
        float *wvp = wV + (size_t)d * 128 + c0;
        #pragma unroll
        for (int i = 0; i < 8; i++) {
            const float w = (i < 4) ? wA : wB;
            const float4 vv = *reinterpret_cast<const float4 *>(vr + 4 * i);
            atomicAdd(wvp + 4 * i + 0, vv.x * w);
            atomicAdd(wvp + 4 * i + 1, vv.y * w);
            atomicAdd(wvp + 4 * i + 2, vv.z * w);
            atomicAdd(wvp + 4 * i + 3, vv.w * w);
        }
        atomicAdd(z + (size_t)d * 8 + (c0 >> 4),     wA);
        atomicAdd(z + (size_t)d * 8 + (c0 >> 4) + 1, wB);

        store_cvt(Au, eo, r, c0);          // overwrite A with e_out
    }
    __syncthreads();

    // ---- GEMM2: proj = eo @ Wo_e ----
    ZERO_ACC(acc);
    CP_WAIT(1); __syncthreads();
    mma_tile(acc, Ac, 0, w0, mw, nw, lane);
    __syncthreads();
    loadW(w0, W1, 128, 0, 0, tid); CP_COMMIT();
    CP_WAIT(1); __syncthreads();
    mma_tile(acc, Ac, 64, w1, mw, nw, lane);
    __syncthreads();
    loadW(w1, W1, 128, 0, 64, tid); CP_COMMIT();

    stage_pst(acc, Pst, bo, mw, nw, lane);   // Pst = proj + bias

    // ---- LN2e + MLP + residuals -> Y --------------------------------------
    mlp_tail(Ac, Hc, Pst, w0, w1, ln2w, ln2b, W1, W2,
             edge, Y, row0, EE, tid, lane, mw, nw);
}

// ============ node megakernel: wV/z + Wo_n + LN2n + MLP ====================
__global__ void __launch_bounds__(256, 2) wo_mlp(
    const float *__restrict__ wVin, const float *__restrict__ zdiv,
    const float *__restrict__ node,
    const __half *__restrict__ Wo, const float *__restrict__ bo,
    const float *__restrict__ ln2w, const float *__restrict__ ln2b,
    const __half *__restrict__ W1, const __half *__restrict__ W2,
    float *__restrict__ Y, int R)
{
    extern __shared__ char smc[];
    char *Ac = smc + M_A;
    char *Hc = smc + M_H;
    uint32_t *Au = reinterpret_cast<uint32_t *>(Ac);
    float *Pst = reinterpret_cast<float *>(smc + M_P);
    char *w0 = smc + M_W0;
    char *w1 = smc + M_W1;

    const int tid  = threadIdx.x;
    const int wid  = tid >> 5;
    const int lane = tid & 31;
    const int mw   = wid & 1;
    const int nw   = wid >> 1;
    const int row0 = blockIdx.x * 64;

    loadW(w0, Wo, 128, 0, 0, tid);  CP_COMMIT();
    loadW(w1, Wo, 128, 0, 64, tid); CP_COMMIT();

    // ---- A: wV rows / z -> fp16 smem --------------------------------------
    {
        const int r  = tid >> 2;
        const int c0 = (tid & 3) * 32;
        const int grow = row0 + r;
        float4 v[8];
        if (grow < R) {
            const float4 *xr = reinterpret_cast<const float4 *>(
                wVin + (size_t)grow * 128 + c0);
            #pragma unroll
            for (int i = 0; i < 8; i++) v[i] = xr[i];
            const float rA = 1.f / (zdiv[(size_t)grow * 8 + (c0 >> 4)] + 1e-8f);
            const float rB = 1.f / (zdiv[(size_t)grow * 8 + (c0 >> 4) + 1] + 1e-8f);
            #pragma unroll
            for (int i = 0; i < 8; i++) {
                const float s = (i < 4) ? rA : rB;
                v[i].x *= s; v[i].y *= s; v[i].z *= s; v[i].w *= s;
            }
        } else {
            #pragma unroll
            for (int i = 0; i < 8; i++) v[i] = make_float4(0.f, 0.f, 0.f, 0.f);
        }
        store_cvt(Au, v, r, c0);
    }

    // ---- GEMM: proj = A @ Wo_n ----
    float acc[2][4][4];
    ZERO_ACC(acc);
    CP_WAIT(1); __syncthreads();
    mma_tile(acc, Ac, 0, w0, mw, nw, lane);
    __syncthreads();
    loadW(w0, W1, 128, 0, 0, tid); CP_COMMIT();
    CP_WAIT(1); __syncthreads();
    mma_tile(acc, Ac, 64, w1, mw, nw, lane);
    __syncthreads();
    loadW(w1, W1, 128, 0, 64, tid); CP_COMMIT();

    stage_pst(acc, Pst, bo, mw, nw, lane);   // Pst = proj + bias

    mlp_tail(Ac, Hc, Pst, w0, w1, ln2w, ln2b, W1, W2,
             node, Y, row0, R, tid, lane, mw, nw);
}

// --------------- single-launch weight convert/transpose --------------------
struct WDesc { const float *W; int K; int No; int ofs; int start; };
struct WPack { WDesc d[10]; int total; };

__global__ void split_all(WPack p, __half *__restrict__ out)
{
    int i = blockIdx.x * 256 + threadIdx.x;
    if (i >= p.total) return;
    #pragma unroll
    for (int m = 0; m < 10; m++) {
        const WDesc &d = p.d[m];
        const int sz = d.K * d.No;
        if (i < d.start + sz) {
            const int il = i - d.start;
            const int k = il / d.No;
            const int n = il - k * d.No;
            out[(size_t)d.ofs + (size_t)n * d.K + k] = __float2half(d.W[il]);
            return;
        }
    }
}

__global__ void pack_bias(const float *__restrict__ a, const float *__restrict__ b,
                          const float *__restrict__ c, float *__restrict__ o)
{
    const int i = threadIdx.x;
    if (i < 128) { o[i] = a[i]; o[128 + i] = b[i]; o[256 + i] = c[i]; }
}

// ---------------------------------------------------------------------------
extern "C" void kernel_launch(void *const *d_in, const int *in_sizes, int n_in,
                              void *d_out, int out_size)
{
    const float *node   = (const float *)d_in[0];
    const float *edge   = (const float *)d_in[1];
    const int   *src    = (const int *)d_in[2];
    const int   *dst    = (const int *)d_in[3];
    const float *ln1n_w = (const float *)d_in[4];
    const float *ln1n_b = (const float *)d_in[5];
    const float *ln1e_w = (const float *)d_in[6];
    const float *ln1e_b = (const float *)d_in[7];
    const float *ln2n_w = (const float *)d_in[8];
    const float *ln2n_b = (const float *)d_in[9];
    const float *ln2e_w = (const float *)d_in[10];
    const float *ln2e_b = (const float *)d_in[11];
    const float *Wq = (const float *)d_in[12];  const float *bq = (const float *)d_in[13];
    const float *Wk = (const float *)d_in[14];  const float *bk = (const float *)d_in[15];
    const float *Wv = (const float *)d_in[16];  const float *bv = (const float *)d_in[17];
    const float *We = (const float *)d_in[18];  const float *be = (const float *)d_in[19];
    const float *Wo_n = (const float *)d_in[20]; const float *bo_n = (const float *)d_in[21];
    const float *Wo_e = (const float *)d_in[22]; const float *bo_e = (const float *)d_in[23];
    const float *w1n = (const float *)d_in[24];
    const float *w2n = (const float *)d_in[25];
    const float *w1e = (const float *)d_in[26];
    const float *w2e = (const float *)d_in[27];

    float *outh = (float *)d_out;
    float *oute = outh + (size_t)NN * DD;

    float *QKVp, *wVp, *zp, *bqkv;
    __half *WFp;
    cudaGetSymbolAddress((void **)&QKVp, g_QKV);
    cudaGetSymbolAddress((void **)&wVp, g_wV);
    cudaGetSymbolAddress((void **)&zp,  g_z);
    cudaGetSymbolAddress((void **)&bqkv, g_bqkv);
    cudaGetSymbolAddress((void **)&WFp, g_WF);

    cudaFuncSetAttribute(tcgemm,    cudaFuncAttributeMaxDynamicSharedMemorySize, G_TOT);
    cudaFuncSetAttribute(edge_mega, cudaFuncAttributeMaxDynamicSharedMemorySize, M_TOT);
    cudaFuncSetAttribute(wo_mlp,    cudaFuncAttributeMaxDynamicSharedMemorySize, M_TOT);

    WPack p;
    int st = 0;
    auto add = [&](int m, const float *W, int K, int No, int ofs) {
        p.d[m] = {W, K, No, ofs, st};
        st += K * No;
    };
    add(0, Wq, 128, 128, OF_QKV);
    add(1, Wk, 128, 128, OF_QKV + 16384);
    add(2, Wv, 128, 128, OF_QKV + 32768);
    add(3, We, 128, 128, OF_WE);
    add(4, Wo_n, 128, 128, OF_WON);
    add(5, Wo_e, 128, 128, OF_WOE);
    add(6, w1n, 128, 256, OF_W1N);
    add(7, w2n, 256, 128, OF_W2N);
    add(8, w1e, 128, 256, OF_W1E);
    add(9, w2e, 256, 128, OF_W2E);
    p.total = st;
    split_all<<<(st + 255) / 256, 256>>>(p, WFp);
    pack_bias<<<1, 128>>>(bq, bk, bv, bqkv);

    cudaMemsetAsync(wVp, 0, (size_t)NN * DD * sizeof(float), 0);
    cudaMemsetAsync(zp,  0, (size_t)NN * HH * sizeof(float), 0);

    const int GN = (NN + 63) / 64;
    const int GE = EE / 64;

    // LN1 + fused QKV projection (No=384) -> QKV table
    tcgemm<<<GN, 256, G_TOT>>>(node, 128, ln1n_w, ln1n_b,
                               WFp + OF_QKV, 384, bqkv, QKVp, 384, NN);

    // edge megakernel: everything edge-side -> oute (+ wV, z scatters)
    edge_mega<<<GE, 256, M_TOT>>>(edge, ln1e_w, ln1e_b, QKVp, src, dst,
                                  WFp + OF_WE, be, WFp + OF_WOE, bo_e,
                                  ln2e_w, ln2e_b, WFp + OF_W1E, WFp + OF_W2E,
                                  wVp, zp, oute);

    // node megakernel: wV/z + Wo_n + LN2n + MLP -> outh
    wo_mlp<<<GN, 256, M_TOT>>>(wVp, zp, node,
                               WFp + OF_WON, bo_n,
                               ln2n_w, ln2n_b, WFp + OF_W1N, WFp + OF_W2N,
                               outh, NN);
}